// round 1
// baseline (speedup 1.0000x reference)
#include <cuda_runtime.h>
#include <math.h>

// Problem constants
constexpr int B  = 64;
constexpr int H  = 1024;
constexpr int E  = 1024;
constexpr int SEQ = 1024;
constexpr int V  = 50257;
constexpr long long BV = (long long)B * V;

// ---------------- scratch (static device memory; no allocs) ----------------
__device__ float g_gi[8 * 3 * H * B];        // GRU input-gate partials  [split][row][b]
__device__ float g_gh[8 * 3 * H * B];        // GRU hidden-gate partials
__device__ float g_hnew[B * H];              // new hidden state [b][h]
__device__ float g_pm[B * 16];               // attention chunk max
__device__ float g_pl[B * 16];               // attention chunk sum
__device__ float g_pctx[B * 16 * H];         // attention chunk context
__device__ float g_ctx[B * H];               // context [b][h]
__device__ float g_cpart[8 * H * B];         // concat-gemm partials [split][n][b]
__device__ float g_co[B * H];                // concat_out (tanh) [b][n]
__device__ float g_lse[B];                   // log-sum-exp per row

// ---------------- f32x2 packed-FMA helpers (sm_10x) ----------------
static __device__ __forceinline__ unsigned long long ffma2(
    unsigned long long a, unsigned long long b, unsigned long long c) {
    unsigned long long d;
    asm("fma.rn.f32x2 %0, %1, %2, %3;" : "=l"(d) : "l"(a), "l"(b), "l"(c));
    return d;
}
static __device__ __forceinline__ unsigned long long dup2(float x) {
    unsigned long long d;
    asm("mov.b64 %0, {%1, %1};" : "=l"(d) : "f"(x));
    return d;
}
static __device__ __forceinline__ float2 unpack2(unsigned long long v) {
    float2 r;
    asm("mov.b64 {%0, %1}, %2;" : "=f"(r.x), "=f"(r.y) : "l"(v));
    return r;
}

// ---------------- generic tiled GEMM: C[64 x NTOT] = A[64 x KTOT] @ W[NTOT x KTOT]^T
// MODE 0: A = emb[gather(idx)]            -> partials g_gi
// MODE 1: A = last_hidden (param)         -> partials g_gh
// MODE 2: A = concat(g_hnew, g_ctx)       -> partials g_cpart
// MODE 3: A = g_co, +bias, direct logits  -> d_out
// Block tile: 64b x 256n, 256 threads, thread tile 8b x 8n using f32x2 FFMA2.
template<int MODE, int NTOT, int KTOT, int SPLITS>
__global__ __launch_bounds__(256) void gemm64(
    const float* __restrict__ A,
    const int*   __restrict__ gidx,
    const float* __restrict__ emb,
    const float* __restrict__ Wm,
    const float* __restrict__ bias,
    float*       __restrict__ doutp)
{
    __shared__ __align__(16) float As[16][64];
    __shared__ __align__(16) float Ws[16][256];
    __shared__ int sidx[64];

    const int t  = threadIdx.x;
    const int n0 = blockIdx.x * 256;
    constexpr int KSPL = KTOT / SPLITS;
    const int kstart = blockIdx.y * KSPL;

    if (MODE == 0) {
        if (t < 64) sidx[t] = gidx[t];
        __syncthreads();
    }

    unsigned long long acc[8][4];
    #pragma unroll
    for (int i = 0; i < 8; i++)
        #pragma unroll
        for (int j = 0; j < 4; j++) acc[i][j] = 0ull;

    const int tb  = t >> 5;   // 0..7  : b-group (8 b's)
    const int tv  = t & 31;   // 0..31 : n-group (8 n's)
    const int sb  = t & 63;   // staging b
    const int skq = t >> 6;   // staging k-quad
    const int sr  = t >> 2;   // staging W row base
    const int sfq = t & 3;    // staging W float4 idx

    for (int k0 = kstart; k0 < kstart + KSPL; k0 += 16) {
        // stage A chunk [16k x 64b]
        {
            int kg = k0 + skq * 4;
            float4 v;
            if (MODE == 0) {
                const float* row = emb + (size_t)sidx[sb] * E;
                v = *(const float4*)(row + kg);
            } else if (MODE == 1) {
                v = *(const float4*)(A + sb * H + kg);
            } else if (MODE == 2) {
                v = (kg < H) ? *(const float4*)(g_hnew + sb * H + kg)
                             : *(const float4*)(g_ctx  + sb * H + (kg - H));
            } else {
                v = *(const float4*)(g_co + sb * H + kg);
            }
            As[skq*4+0][sb] = v.x; As[skq*4+1][sb] = v.y;
            As[skq*4+2][sb] = v.z; As[skq*4+3][sb] = v.w;
        }
        // stage W chunk [16k x 256n]
        #pragma unroll
        for (int p = 0; p < 4; p++) {
            int r = p * 64 + sr;
            int n = n0 + r;
            float4 v = make_float4(0.f, 0.f, 0.f, 0.f);
            if ((NTOT % 256 == 0) || (n < NTOT))
                v = *(const float4*)(Wm + (size_t)n * KTOT + k0 + sfq * 4);
            Ws[sfq*4+0][r] = v.x; Ws[sfq*4+1][r] = v.y;
            Ws[sfq*4+2][r] = v.z; Ws[sfq*4+3][r] = v.w;
        }
        __syncthreads();

        #pragma unroll
        for (int kk = 0; kk < 16; kk++) {
            ulonglong2 aA = *(const ulonglong2*)(&As[kk][tb*8]);
            ulonglong2 aB = *(const ulonglong2*)(&As[kk][tb*8] + 4);
            float4 w0 = *(const float4*)(&Ws[kk][tv*8]);
            float4 w1 = *(const float4*)(&Ws[kk][tv*8] + 4);
            float wv[8] = {w0.x, w0.y, w0.z, w0.w, w1.x, w1.y, w1.z, w1.w};
            #pragma unroll
            for (int wi = 0; wi < 8; wi++) {
                unsigned long long w2 = dup2(wv[wi]);
                acc[wi][0] = ffma2(aA.x, w2, acc[wi][0]);
                acc[wi][1] = ffma2(aA.y, w2, acc[wi][1]);
                acc[wi][2] = ffma2(aB.x, w2, acc[wi][2]);
                acc[wi][3] = ffma2(aB.y, w2, acc[wi][3]);
            }
        }
        __syncthreads();
    }

    // epilogue
    float* outp = (MODE == 0) ? g_gi : (MODE == 1) ? g_gh : (MODE == 2) ? g_cpart : doutp;
    #pragma unroll
    for (int wi = 0; wi < 8; wi++) {
        int n = n0 + tv * 8 + wi;
        if (n < NTOT) {
            if (MODE == 3) {
                float bb = bias[n];
                #pragma unroll
                for (int j = 0; j < 4; j++) {
                    float2 c = unpack2(acc[wi][j]);
                    int b0 = tb * 8 + 2 * j;
                    outp[(size_t)b0 * V + n]       = c.x + bb;
                    outp[(size_t)(b0 + 1) * V + n] = c.y + bb;
                }
            } else {
                float* o = outp + ((size_t)blockIdx.y * NTOT + n) * 64 + tb * 8;
                #pragma unroll
                for (int j = 0; j < 4; j++) {
                    float2 c = unpack2(acc[wi][j]);
                    o[2*j] = c.x; o[2*j + 1] = c.y;
                }
            }
        }
    }
}

// ---------------- GRU gates: combine gi/gh partials, compute h_new ----------------
__global__ void gru_gates(const float* __restrict__ lh, const float* __restrict__ b_ih,
                          const float* __restrict__ b_hh, float* __restrict__ dout)
{
    int idx = blockIdx.x * 256 + threadIdx.x;   // 0..65535
    int j = idx >> 6, b = idx & 63;
    float ir = 0.f, iz = 0.f, inn = 0.f, hr = 0.f, hz = 0.f, hn = 0.f;
    #pragma unroll
    for (int s = 0; s < 8; s++) {
        const float* gi = g_gi + (size_t)s * (3 * H * 64);
        const float* gh = g_gh + (size_t)s * (3 * H * 64);
        ir  += gi[j*64 + b];            hr  += gh[j*64 + b];
        iz  += gi[(H + j)*64 + b];      hz  += gh[(H + j)*64 + b];
        inn += gi[(2*H + j)*64 + b];    hn  += gh[(2*H + j)*64 + b];
    }
    ir += b_ih[j]; iz += b_ih[H + j]; inn += b_ih[2*H + j];
    hr += b_hh[j]; hz += b_hh[H + j]; hn  += b_hh[2*H + j];
    float r = 1.f / (1.f + expf(-(ir + hr)));
    float z = 1.f / (1.f + expf(-(iz + hz)));
    float n = tanhf(inn + r * hn);
    float h = lh[b * H + j];
    float hnew = (1.f - z) * n + z * h;
    g_hnew[b * H + j] = hnew;
    dout[BV + (size_t)b * H + j] = hnew;    // hidden output
}

// ---------------- attention: per (b, s-chunk) partial softmax + context ----------------
__global__ __launch_bounds__(256) void attn_partial(const float* __restrict__ enc)
{
    __shared__ __align__(16) float hn[H];
    __shared__ float sc[64];
    __shared__ float pr[64];
    const int t = threadIdx.x;
    const int sp = blockIdx.x, b = blockIdx.y;

    ((float4*)hn)[t] = ((const float4*)(g_hnew + (size_t)b * H))[t];
    __syncthreads();

    const int w = t >> 5, lane = t & 31;
    const float4* hn4 = (const float4*)hn;
    #pragma unroll
    for (int i = 0; i < 8; i++) {
        int s = sp * 64 + w * 8 + i;
        const float4* e4 = (const float4*)(enc + ((size_t)b * SEQ + s) * H);
        float a = 0.f;
        #pragma unroll
        for (int k = 0; k < 8; k++) {
            float4 ev = e4[lane + 32 * k];
            float4 hv = hn4[lane + 32 * k];
            a += ev.x*hv.x + ev.y*hv.y + ev.z*hv.z + ev.w*hv.w;
        }
        #pragma unroll
        for (int o = 16; o > 0; o >>= 1) a += __shfl_down_sync(0xffffffffu, a, o);
        if (lane == 0) sc[w * 8 + i] = a;
    }
    __syncthreads();

    float m = -1e30f;
    #pragma unroll
    for (int i = 0; i < 64; i++) m = fmaxf(m, sc[i]);
    if (t < 64) pr[t] = expf(sc[t] - m);
    __syncthreads();
    float l = 0.f;
    #pragma unroll
    for (int i = 0; i < 64; i++) l += pr[i];

    // context partial (chunk rows are L1/L2-hot from the score pass)
    float4 acc = make_float4(0.f, 0.f, 0.f, 0.f);
    const int j4 = t * 4;
    #pragma unroll 4
    for (int s = 0; s < 64; s++) {
        float p = pr[s];
        float4 ev = *(const float4*)(enc + ((size_t)b * SEQ + sp * 64 + s) * H + j4);
        acc.x += p * ev.x; acc.y += p * ev.y; acc.z += p * ev.z; acc.w += p * ev.w;
    }
    *(float4*)(g_pctx + ((size_t)(b * 16 + sp)) * H + j4) = acc;
    if (t == 0) { g_pm[b * 16 + sp] = m; g_pl[b * 16 + sp] = l; }
}

__global__ void attn_combine()
{
    const int b = blockIdx.x, t = threadIdx.x;
    float M = -1e30f;
    #pragma unroll
    for (int c = 0; c < 16; c++) M = fmaxf(M, g_pm[b * 16 + c]);
    float e[16]; float L = 0.f;
    #pragma unroll
    for (int c = 0; c < 16; c++) { e[c] = expf(g_pm[b*16 + c] - M); L += g_pl[b*16 + c] * e[c]; }
    float inv = 1.f / L;
    int j4 = t * 4;
    float4 acc = make_float4(0.f, 0.f, 0.f, 0.f);
    #pragma unroll
    for (int c = 0; c < 16; c++) {
        float4 v = *(const float4*)(g_pctx + ((size_t)(b * 16 + c)) * H + j4);
        float wv = e[c];
        acc.x += wv * v.x; acc.y += wv * v.y; acc.z += wv * v.z; acc.w += wv * v.w;
    }
    *(float4*)(g_ctx + (size_t)b * H + j4) =
        make_float4(acc.x * inv, acc.y * inv, acc.z * inv, acc.w * inv);
}

// ---------------- concat-gemm combine: bias + tanh ----------------
__global__ void cat_combine(const float* __restrict__ cbias)
{
    int idx = blockIdx.x * 256 + threadIdx.x;   // 65536
    int n = idx >> 6, b = idx & 63;
    float s = cbias[n];
    #pragma unroll
    for (int sp = 0; sp < 8; sp++) s += g_cpart[((size_t)sp * H + n) * 64 + b];
    g_co[b * H + n] = tanhf(s);
}

// ---------------- log-softmax ----------------
__global__ void lse_kernel(const float* __restrict__ dout)
{
    __shared__ float red[256];
    const int b = blockIdx.x, t = threadIdx.x;
    const float* row = dout + (size_t)b * V;
    float m = -1e30f;
    for (int v = t; v < V; v += 256) m = fmaxf(m, row[v]);
    red[t] = m; __syncthreads();
    for (int s = 128; s > 0; s >>= 1) { if (t < s) red[t] = fmaxf(red[t], red[t + s]); __syncthreads(); }
    float bm = red[0]; __syncthreads();
    float sum = 0.f;
    for (int v = t; v < V; v += 256) sum += expf(row[v] - bm);
    red[t] = sum; __syncthreads();
    for (int s = 128; s > 0; s >>= 1) { if (t < s) red[t] += red[t + s]; __syncthreads(); }
    if (t == 0) g_lse[b] = bm + logf(red[0]);
}

__global__ void sub_kernel(float* __restrict__ dout)
{
    int i = blockIdx.x * 256 + threadIdx.x;
    if (i < V) dout[(size_t)blockIdx.y * V + i] -= g_lse[blockIdx.y];
}

// ---------------- launch ----------------
extern "C" void kernel_launch(void* const* d_in, const int* in_sizes, int n_in,
                              void* d_out, int out_size)
{
    const int*   seq = (const int*)  d_in[0];
    const float* lh  = (const float*)d_in[1];
    const float* enc = (const float*)d_in[2];
    const float* emb = (const float*)d_in[3];
    const float* wih = (const float*)d_in[4];
    const float* whh = (const float*)d_in[5];
    const float* bih = (const float*)d_in[6];
    const float* bhh = (const float*)d_in[7];
    const float* cw  = (const float*)d_in[8];
    const float* cb  = (const float*)d_in[9];
    const float* ow  = (const float*)d_in[10];
    const float* ob  = (const float*)d_in[11];
    float* dout = (float*)d_out;
    (void)in_sizes; (void)n_in; (void)out_size;

    // GRU gate GEMMs (split-K = 8)
    gemm64<0, 3*H, E, 8><<<dim3(12, 8), 256>>>(nullptr, seq, emb, wih, nullptr, nullptr);
    gemm64<1, 3*H, H, 8><<<dim3(12, 8), 256>>>(lh, nullptr, nullptr, whh, nullptr, nullptr);
    gru_gates<<<256, 256>>>(lh, bih, bhh, dout);

    // attention (single HBM pass over encoder_outputs)
    attn_partial<<<dim3(16, 64), 256>>>(enc);
    attn_combine<<<64, 256>>>();

    // concat GEMM (split-K = 8) + tanh
    gemm64<2, H, 2*H, 8><<<dim3(4, 8), 256>>>(nullptr, nullptr, nullptr, cw, nullptr, nullptr);
    cat_combine<<<256, 256>>>(cb);

    // output GEMM -> logits directly into d_out
    gemm64<3, V, H, 1><<<dim3((V + 255) / 256, 1), 256>>>(nullptr, nullptr, nullptr, ow, ob, dout);

    // log-softmax
    lse_kernel<<<64, 256>>>(dout);
    sub_kernel<<<dim3((V + 255) / 256, 64), 256>>>(dout);
}

// round 2
// speedup vs baseline: 1.8127x; 1.8127x over previous
#include <cuda_runtime.h>
#include <cuda_bf16.h>
#include <math.h>

// Problem constants
constexpr int B  = 64;
constexpr int H  = 1024;
constexpr int E  = 1024;
constexpr int SEQ = 1024;
constexpr int V  = 50257;
constexpr long long BV = (long long)B * V;

// ---------------- scratch (static device memory; no allocs) ----------------
__device__ float g_gi[8 * 3 * H * B];        // GRU input-gate partials  [split][row][b]
__device__ float g_gh[8 * 3 * H * B];        // GRU hidden-gate partials
__device__ float g_hnew[B * H];              // new hidden state [b][h]
__device__ float g_pm[B * 16];               // attention chunk max
__device__ float g_pl[B * 16];               // attention chunk sum
__device__ float g_pctx[B * 16 * H];         // attention chunk context
__device__ float g_ctx[B * H];               // context [b][h]
__device__ float g_cpart[8 * H * B];         // concat-gemm partials [split][n][b]
__device__ __nv_bfloat16 g_co_bf[B * H];     // concat_out (tanh) bf16 [b][n]
__device__ float g_lse[B];                   // log-sum-exp per row

// ---------------- f32x2 packed-FMA helpers (sm_10x) ----------------
static __device__ __forceinline__ unsigned long long ffma2(
    unsigned long long a, unsigned long long b, unsigned long long c) {
    unsigned long long d;
    asm("fma.rn.f32x2 %0, %1, %2, %3;" : "=l"(d) : "l"(a), "l"(b), "l"(c));
    return d;
}
static __device__ __forceinline__ unsigned long long dup2(float x) {
    unsigned long long d;
    asm("mov.b64 %0, {%1, %1};" : "=l"(d) : "f"(x));
    return d;
}
static __device__ __forceinline__ float2 unpack2(unsigned long long v) {
    float2 r;
    asm("mov.b64 {%0, %1}, %2;" : "=f"(r.x), "=f"(r.y) : "l"(v));
    return r;
}

// ---------------- tensor-core helpers ----------------
static __device__ __forceinline__ void ldm_x4(unsigned& r0, unsigned& r1,
                                              unsigned& r2, unsigned& r3, const void* p) {
    unsigned addr = (unsigned)__cvta_generic_to_shared(p);
    asm volatile("ldmatrix.sync.aligned.m8n8.x4.shared.b16 {%0,%1,%2,%3}, [%4];"
                 : "=r"(r0), "=r"(r1), "=r"(r2), "=r"(r3) : "r"(addr));
}
static __device__ __forceinline__ void mma16816(float* d, const unsigned* a,
                                                unsigned b0, unsigned b1) {
    asm volatile(
        "mma.sync.aligned.m16n8k16.row.col.f32.bf16.bf16.f32 "
        "{%0,%1,%2,%3}, {%4,%5,%6,%7}, {%8,%9}, {%0,%1,%2,%3};"
        : "+f"(d[0]), "+f"(d[1]), "+f"(d[2]), "+f"(d[3])
        : "r"(a[0]), "r"(a[1]), "r"(a[2]), "r"(a[3]), "r"(b0), "r"(b1));
}
static __device__ __forceinline__ unsigned pack_bf2(float lo, float hi) {
    __nv_bfloat162 v = __floats2bfloat162_rn(lo, hi);
    return *reinterpret_cast<unsigned*>(&v);
}

// ---------------- generic small tiled GEMM (fp32, FFMA2): C[64 x NTOT] = A @ W^T
// MODE 0: A = emb[gather(idx)]  -> partials g_gi
// MODE 1: A = last_hidden       -> partials g_gh
// MODE 2: A = concat(g_hnew, g_ctx) -> partials g_cpart
template<int MODE, int NTOT, int KTOT, int SPLITS>
__global__ __launch_bounds__(256) void gemm64(
    const float* __restrict__ A,
    const int*   __restrict__ gidx,
    const float* __restrict__ emb,
    const float* __restrict__ Wm)
{
    __shared__ __align__(16) float As[16][64];
    __shared__ __align__(16) float Ws[16][256];
    __shared__ int sidx[64];

    const int t  = threadIdx.x;
    const int n0 = blockIdx.x * 256;
    constexpr int KSPL = KTOT / SPLITS;
    const int kstart = blockIdx.y * KSPL;

    if (MODE == 0) {
        if (t < 64) sidx[t] = gidx[t];
        __syncthreads();
    }

    unsigned long long acc[8][4];
    #pragma unroll
    for (int i = 0; i < 8; i++)
        #pragma unroll
        for (int j = 0; j < 4; j++) acc[i][j] = 0ull;

    const int tb  = t >> 5;
    const int tv  = t & 31;
    const int sb  = t & 63;
    const int skq = t >> 6;
    const int sr  = t >> 2;
    const int sfq = t & 3;

    for (int k0 = kstart; k0 < kstart + KSPL; k0 += 16) {
        {
            int kg = k0 + skq * 4;
            float4 v;
            if (MODE == 0) {
                const float* row = emb + (size_t)sidx[sb] * E;
                v = *(const float4*)(row + kg);
            } else if (MODE == 1) {
                v = *(const float4*)(A + sb * H + kg);
            } else {
                v = (kg < H) ? *(const float4*)(g_hnew + sb * H + kg)
                             : *(const float4*)(g_ctx  + sb * H + (kg - H));
            }
            As[skq*4+0][sb] = v.x; As[skq*4+1][sb] = v.y;
            As[skq*4+2][sb] = v.z; As[skq*4+3][sb] = v.w;
        }
        #pragma unroll
        for (int p = 0; p < 4; p++) {
            int r = p * 64 + sr;
            int n = n0 + r;
            float4 v = make_float4(0.f, 0.f, 0.f, 0.f);
            if ((NTOT % 256 == 0) || (n < NTOT))
                v = *(const float4*)(Wm + (size_t)n * KTOT + k0 + sfq * 4);
            Ws[sfq*4+0][r] = v.x; Ws[sfq*4+1][r] = v.y;
            Ws[sfq*4+2][r] = v.z; Ws[sfq*4+3][r] = v.w;
        }
        __syncthreads();

        #pragma unroll
        for (int kk = 0; kk < 16; kk++) {
            ulonglong2 aA = *(const ulonglong2*)(&As[kk][tb*8]);
            ulonglong2 aB = *(const ulonglong2*)(&As[kk][tb*8] + 4);
            float4 w0 = *(const float4*)(&Ws[kk][tv*8]);
            float4 w1 = *(const float4*)(&Ws[kk][tv*8] + 4);
            float wv[8] = {w0.x, w0.y, w0.z, w0.w, w1.x, w1.y, w1.z, w1.w};
            #pragma unroll
            for (int wi = 0; wi < 8; wi++) {
                unsigned long long w2 = dup2(wv[wi]);
                acc[wi][0] = ffma2(aA.x, w2, acc[wi][0]);
                acc[wi][1] = ffma2(aA.y, w2, acc[wi][1]);
                acc[wi][2] = ffma2(aB.x, w2, acc[wi][2]);
                acc[wi][3] = ffma2(aB.y, w2, acc[wi][3]);
            }
        }
        __syncthreads();
    }

    float* outp = (MODE == 0) ? g_gi : (MODE == 1) ? g_gh : g_cpart;
    #pragma unroll
    for (int wi = 0; wi < 8; wi++) {
        int n = n0 + tv * 8 + wi;
        if (n < NTOT) {
            float* o = outp + ((size_t)blockIdx.y * NTOT + n) * 64 + tb * 8;
            #pragma unroll
            for (int j = 0; j < 4; j++) {
                float2 c = unpack2(acc[wi][j]);
                o[2*j] = c.x; o[2*j + 1] = c.y;
            }
        }
    }
}

// ---------------- GRU gates ----------------
__global__ void gru_gates(const float* __restrict__ lh, const float* __restrict__ b_ih,
                          const float* __restrict__ b_hh, float* __restrict__ dout)
{
    int idx = blockIdx.x * 256 + threadIdx.x;
    int j = idx >> 6, b = idx & 63;
    float ir = 0.f, iz = 0.f, inn = 0.f, hr = 0.f, hz = 0.f, hn = 0.f;
    #pragma unroll
    for (int s = 0; s < 8; s++) {
        const float* gi = g_gi + (size_t)s * (3 * H * 64);
        const float* gh = g_gh + (size_t)s * (3 * H * 64);
        ir  += gi[j*64 + b];            hr  += gh[j*64 + b];
        iz  += gi[(H + j)*64 + b];      hz  += gh[(H + j)*64 + b];
        inn += gi[(2*H + j)*64 + b];    hn  += gh[(2*H + j)*64 + b];
    }
    ir += b_ih[j]; iz += b_ih[H + j]; inn += b_ih[2*H + j];
    hr += b_hh[j]; hz += b_hh[H + j]; hn  += b_hh[2*H + j];
    float r = 1.f / (1.f + expf(-(ir + hr)));
    float z = 1.f / (1.f + expf(-(iz + hz)));
    float n = tanhf(inn + r * hn);
    float h = lh[b * H + j];
    float hnew = (1.f - z) * n + z * h;
    g_hnew[b * H + j] = hnew;
    dout[BV + (size_t)b * H + j] = hnew;
}

// ---------------- attention: single-pass per (b, chunk) with online softmax ----------------
__global__ __launch_bounds__(256) void attn_fused(const float* __restrict__ enc)
{
    __shared__ __align__(16) float hn[H];
    __shared__ __align__(16) float4 sbuf[8][256];
    __shared__ float sm[8], sl[8];
    const int t = threadIdx.x, lane = t & 31, w = t >> 5;
    const int sp = blockIdx.x, b = blockIdx.y;

    ((float4*)hn)[t] = ((const float4*)(g_hnew + (size_t)b * H))[t];
    __syncthreads();
    const float4* hn4 = (const float4*)hn;

    float m = -1e30f, l = 0.f;
    float4 ctx[8];
    #pragma unroll
    for (int k = 0; k < 8; k++) ctx[k] = make_float4(0.f, 0.f, 0.f, 0.f);

    for (int i = 0; i < 8; i++) {
        int s = sp * 64 + w * 8 + i;
        const float4* e4 = (const float4*)(enc + ((size_t)b * SEQ + s) * H);
        float4 ev[8];
        float a = 0.f;
        #pragma unroll
        for (int k = 0; k < 8; k++) {
            ev[k] = e4[lane + 32 * k];
            float4 hv = hn4[lane + 32 * k];
            a += ev[k].x*hv.x + ev[k].y*hv.y + ev[k].z*hv.z + ev[k].w*hv.w;
        }
        #pragma unroll
        for (int o = 16; o > 0; o >>= 1) a += __shfl_xor_sync(0xffffffffu, a, o);
        if (a > m) {
            float sc = expf(m - a);
            l *= sc;
            #pragma unroll
            for (int k = 0; k < 8; k++) {
                ctx[k].x *= sc; ctx[k].y *= sc; ctx[k].z *= sc; ctx[k].w *= sc;
            }
            m = a;
        }
        float p = expf(a - m);
        l += p;
        #pragma unroll
        for (int k = 0; k < 8; k++) {
            ctx[k].x += p * ev[k].x; ctx[k].y += p * ev[k].y;
            ctx[k].z += p * ev[k].z; ctx[k].w += p * ev[k].w;
        }
    }

    if (lane == 0) { sm[w] = m; sl[w] = l; }
    __syncthreads();
    float M = -1e30f;
    #pragma unroll
    for (int w2 = 0; w2 < 8; w2++) M = fmaxf(M, sm[w2]);
    float e = expf(m - M);
    #pragma unroll
    for (int k = 0; k < 8; k++) {
        float4 v = ctx[k];
        sbuf[w][lane + 32 * k] = make_float4(v.x * e, v.y * e, v.z * e, v.w * e);
    }
    float L = 0.f;
    #pragma unroll
    for (int w2 = 0; w2 < 8; w2++) L += sl[w2] * expf(sm[w2] - M);
    __syncthreads();

    float4 acc = make_float4(0.f, 0.f, 0.f, 0.f);
    #pragma unroll
    for (int w2 = 0; w2 < 8; w2++) {
        float4 v = sbuf[w2][t];
        acc.x += v.x; acc.y += v.y; acc.z += v.z; acc.w += v.w;
    }
    *(float4*)(g_pctx + ((size_t)(b * 16 + sp)) * H + t * 4) = acc;
    if (t == 0) { g_pm[b * 16 + sp] = M; g_pl[b * 16 + sp] = L; }
}

__global__ void attn_combine()
{
    const int b = blockIdx.x, t = threadIdx.x;
    float M = -1e30f;
    #pragma unroll
    for (int c = 0; c < 16; c++) M = fmaxf(M, g_pm[b * 16 + c]);
    float e[16]; float L = 0.f;
    #pragma unroll
    for (int c = 0; c < 16; c++) { e[c] = expf(g_pm[b*16 + c] - M); L += g_pl[b*16 + c] * e[c]; }
    float inv = 1.f / L;
    int j4 = t * 4;
    float4 acc = make_float4(0.f, 0.f, 0.f, 0.f);
    #pragma unroll
    for (int c = 0; c < 16; c++) {
        float4 v = *(const float4*)(g_pctx + ((size_t)(b * 16 + c)) * H + j4);
        float wv = e[c];
        acc.x += wv * v.x; acc.y += wv * v.y; acc.z += wv * v.z; acc.w += wv * v.w;
    }
    *(float4*)(g_ctx + (size_t)b * H + j4) =
        make_float4(acc.x * inv, acc.y * inv, acc.z * inv, acc.w * inv);
}

// ---------------- concat-gemm combine: bias + tanh -> bf16 A ----------------
__global__ void cat_combine(const float* __restrict__ cbias)
{
    int idx = blockIdx.x * 256 + threadIdx.x;
    int n = idx >> 6, b = idx & 63;
    float s = cbias[n];
    #pragma unroll
    for (int sp = 0; sp < 8; sp++) s += g_cpart[((size_t)sp * H + n) * 64 + b];
    g_co_bf[b * H + n] = __float2bfloat16(tanhf(s));
}

// ---------------- output GEMM: bf16 tensor cores, weights converted on the fly --------
// C[64 x V] = co[64 x 1024] @ out_w[V x 1024]^T + bias.  Block tile 64 x 128, KC=32.
__global__ __launch_bounds__(256) void out_gemm(const float* __restrict__ ow,
                                                const float* __restrict__ ob,
                                                float* __restrict__ dout)
{
    constexpr int KC = 32, NB = 128, STR = 40;   // STR: padded smem row stride (bf16 elems)
    __shared__ unsigned short As[2][64 * STR];
    __shared__ unsigned short Bs[2][NB * STR];

    const int t = threadIdx.x, lane = t & 31, warp = t >> 5;
    const int n0 = blockIdx.x * NB;
    const int wm = warp & 1, wn = warp >> 1;     // warp tile: M32 x N32

    float acc[2][4][4];
    #pragma unroll
    for (int i = 0; i < 2; i++)
        #pragma unroll
        for (int j = 0; j < 4; j++)
            #pragma unroll
            for (int r = 0; r < 4; r++) acc[i][j][r] = 0.f;

    // loader roles
    const int a_row = t >> 2, a_seg = t & 3;     // A: 8 bf16 per thread
    const int b_row = t >> 1, b_half = t & 1;    // B: 16 fp32 per thread
    const bool b_ok = (n0 + b_row) < V;
    const float* bsrc = ow + (size_t)(b_ok ? (n0 + b_row) : 0) * 1024 + b_half * 16;
    const unsigned* a_src = (const unsigned*)g_co_bf + a_row * (H / 2) + a_seg * 4;

    uint4 af;
    float4 bf[4];

    auto load_chunk = [&](int k0) {
        af = *(const uint4*)(a_src + (k0 >> 1));
        #pragma unroll
        for (int i = 0; i < 4; i++) bf[i] = *(const float4*)(bsrc + k0 + i * 4);
    };
    auto store_chunk = [&](int buf) {
        *(uint4*)&As[buf][a_row * STR + a_seg * 8] = af;
        unsigned bb[8];
        #pragma unroll
        for (int i = 0; i < 4; i++) {
            bb[2*i]   = pack_bf2(bf[i].x, bf[i].y);
            bb[2*i+1] = pack_bf2(bf[i].z, bf[i].w);
        }
        *(uint4*)&Bs[buf][b_row * STR + b_half * 16]     = make_uint4(bb[0], bb[1], bb[2], bb[3]);
        *(uint4*)&Bs[buf][b_row * STR + b_half * 16 + 8] = make_uint4(bb[4], bb[5], bb[6], bb[7]);
    };
    auto compute = [&](int buf) {
        #pragma unroll
        for (int ks = 0; ks < 2; ks++) {
            unsigned afr[2][4];
            #pragma unroll
            for (int tm = 0; tm < 2; tm++) {
                int row = wm * 32 + tm * 16 + ((lane >> 3) & 1) * 8 + (lane & 7);
                int col = ks * 16 + (lane >> 4) * 8;
                ldm_x4(afr[tm][0], afr[tm][1], afr[tm][2], afr[tm][3],
                       &As[buf][row * STR + col]);
            }
            unsigned bfr[4][2];
            #pragma unroll
            for (int g = 0; g < 2; g++) {
                int nrow = wn * 32 + g * 16 + (lane >> 4) * 8 + (lane & 7);
                int col  = ks * 16 + ((lane >> 3) & 1) * 8;
                unsigned r0, r1, r2, r3;
                ldm_x4(r0, r1, r2, r3, &Bs[buf][nrow * STR + col]);
                bfr[g*2+0][0] = r0; bfr[g*2+0][1] = r1;
                bfr[g*2+1][0] = r2; bfr[g*2+1][1] = r3;
            }
            #pragma unroll
            for (int tm = 0; tm < 2; tm++)
                #pragma unroll
                for (int tn = 0; tn < 4; tn++)
                    mma16816(acc[tm][tn], afr[tm], bfr[tn][0], bfr[tn][1]);
        }
    };

    load_chunk(0);
    store_chunk(0);
    __syncthreads();

    for (int kc = 0; kc < 32; kc++) {
        int buf = kc & 1;
        if (kc < 31) load_chunk((kc + 1) * KC);
        compute(buf);
        if (kc < 31) store_chunk(buf ^ 1);
        __syncthreads();
    }

    // epilogue: scatter with bias
    const int mrow  = wm * 32 + (lane >> 2);
    const int ncol0 = n0 + wn * 32 + 2 * (lane & 3);
    #pragma unroll
    for (int tm = 0; tm < 2; tm++) {
        #pragma unroll
        for (int tn = 0; tn < 4; tn++) {
            int r = mrow + tm * 16;
            int c = ncol0 + tn * 8;
            if (c < V) {
                float bb = ob[c];
                dout[(size_t)r * V + c]       = acc[tm][tn][0] + bb;
                dout[(size_t)(r + 8) * V + c] = acc[tm][tn][2] + bb;
            }
            if (c + 1 < V) {
                float bb = ob[c + 1];
                dout[(size_t)r * V + c + 1]       = acc[tm][tn][1] + bb;
                dout[(size_t)(r + 8) * V + c + 1] = acc[tm][tn][3] + bb;
            }
        }
    }
}

// ---------------- log-softmax (single-pass online lse, then subtract) ----------------
__global__ void lse_kernel(const float* __restrict__ dout)
{
    __shared__ float rm[256], rl[256];
    const int b = blockIdx.x, t = threadIdx.x;
    const float* row = dout + (size_t)b * V;
    float m = -1e30f, s = 0.f;
    for (int v = t; v < V; v += 256) {
        float x = row[v];
        if (x > m) { s *= expf(m - x); m = x; }
        s += expf(x - m);
    }
    rm[t] = m; rl[t] = s; __syncthreads();
    for (int o = 128; o > 0; o >>= 1) {
        if (t < o) {
            float m2 = fmaxf(rm[t], rm[t + o]);
            rl[t] = rl[t] * expf(rm[t] - m2) + rl[t + o] * expf(rm[t + o] - m2);
            rm[t] = m2;
        }
        __syncthreads();
    }
    if (t == 0) g_lse[b] = rm[0] + logf(rl[0]);
}

__global__ void sub_kernel(float* __restrict__ dout)
{
    int i = blockIdx.x * 256 + threadIdx.x;
    if (i < V) dout[(size_t)blockIdx.y * V + i] -= g_lse[blockIdx.y];
}

// ---------------- launch ----------------
extern "C" void kernel_launch(void* const* d_in, const int* in_sizes, int n_in,
                              void* d_out, int out_size)
{
    const int*   seq = (const int*)  d_in[0];
    const float* lh  = (const float*)d_in[1];
    const float* enc = (const float*)d_in[2];
    const float* emb = (const float*)d_in[3];
    const float* wih = (const float*)d_in[4];
    const float* whh = (const float*)d_in[5];
    const float* bih = (const float*)d_in[6];
    const float* bhh = (const float*)d_in[7];
    const float* cw  = (const float*)d_in[8];
    const float* cb  = (const float*)d_in[9];
    const float* ow  = (const float*)d_in[10];
    const float* ob  = (const float*)d_in[11];
    float* dout = (float*)d_out;
    (void)in_sizes; (void)n_in; (void)out_size;

    // GRU gate GEMMs (split-K = 8)
    gemm64<0, 3*H, E, 8><<<dim3(12, 8), 256>>>(nullptr, seq, emb, wih);
    gemm64<1, 3*H, H, 8><<<dim3(12, 8), 256>>>(lh, nullptr, nullptr, whh);
    gru_gates<<<256, 256>>>(lh, bih, bhh, dout);

    // attention (single HBM pass, registers hold the tile)
    attn_fused<<<dim3(16, 64), 256>>>(enc);
    attn_combine<<<64, 256>>>();

    // concat GEMM (split-K = 8) + tanh -> bf16
    gemm64<2, H, 2*H, 8><<<dim3(4, 8), 256>>>(nullptr, nullptr, nullptr, cw);
    cat_combine<<<256, 256>>>(cb);

    // output GEMM (bf16 tensor cores) -> logits into d_out
    out_gemm<<<(V + 127) / 128, 256>>>(ow, ob, dout);

    // log-softmax
    lse_kernel<<<64, 256>>>(dout);
    sub_kernel<<<dim3((V + 255) / 256, 64), 256>>>(dout);
}